// round 10
// baseline (speedup 1.0000x reference)
#include <cuda_runtime.h>

// Problem constants (fixed by the dataset)
#define NN 50000
#define EE 800000
#define C0 96   // input channels
#define C1 70   // layer-1 out
#define C2 43   // layer-2 out
#define CO 16   // mu / logstd channels

// ---------------- scratch (static __device__ arrays; no allocations) ----------------
__device__ int   g_is64;          // 1 if edge_index buffer is int64 words
__device__ int   g_deg[NN];
__device__ float g_dis[NN];
__device__ float g_dis2[NN];
__device__ int   g_rowptr[NN + 1];
__device__ int   g_cursor[NN];
__device__ int   g_srcs[EE];
__device__ float g_wtag[EE];
__device__ float g_wgcn[EE];
__device__ float g_bufA[NN * C0];   // reused: 96-ch and 70-ch hops
__device__ float g_bufB[NN * C0];
__device__ float g_bufC[NN * C0];
__device__ float g_l1out[NN * C1];
__device__ float g_l2out[NN * C2];
__device__ float g_y[NN * 2 * CO];
__device__ float g_agg[NN * 2 * CO];
__device__ float g_Wc[C2 * 2 * CO];

// Buffer selectors: device code resolves ints -> __device__ globals, so the
// host never touches symbol addresses.
#define SEL_A    0
#define SEL_B    1
#define SEL_C    2
#define SEL_L1   3
#define SEL_L2   4
#define SEL_Y    5
#define SEL_AGG  6
#define SEL_EXT  (-1)

__device__ __forceinline__ float* selbuf(int s) {
    switch (s) {
        case SEL_A:   return g_bufA;
        case SEL_B:   return g_bufB;
        case SEL_C:   return g_bufC;
        case SEL_L1:  return g_l1out;
        case SEL_L2:  return g_l2out;
        case SEL_Y:   return g_y;
        case SEL_AGG: return g_agg;
    }
    return 0;
}

// row index of edge e, col index of edge e, under either word layout
__device__ __forceinline__ int load_row(const int* ei32, int e_cnt, int e) {
    return g_is64 ? ei32[2 * (long long)e] : ei32[e];
}
__device__ __forceinline__ int load_col(const int* ei32, int e_cnt, int e) {
    return g_is64 ? ei32[2 * ((long long)e_cnt + e)] : ei32[e_cnt + e];
}

// ---------------- dtype detection ----------------
// int64 values < 2^31 have zero high (odd, little-endian) words everywhere.
// int32 edge data has random node ids at odd positions -> some nonzero.
__global__ void k_detect(const int* __restrict__ ei32) {
    __shared__ int any;
    if (threadIdx.x == 0) any = 0;
    __syncthreads();
    int local = 0;
    for (int i = threadIdx.x; i < 4096; i += blockDim.x)
        if (ei32[2 * i + 1] != 0) local = 1;
    if (local) atomicOr(&any, 1);
    __syncthreads();
    if (threadIdx.x == 0) g_is64 = (any == 0) ? 1 : 0;
}

// ---------------- graph-structure kernels ----------------
__global__ void k_zero_deg(int n) {
    int i = blockIdx.x * blockDim.x + threadIdx.x;
    if (i < n) g_deg[i] = 0;
}

__global__ void k_hist(const int* __restrict__ ei32, int e_cnt, int n) {
    int e = blockIdx.x * blockDim.x + threadIdx.x;
    if (e >= e_cnt) return;
    int r = load_row(ei32, e_cnt, e);
    int c = load_col(ei32, e_cnt, e);
    if ((unsigned)r < (unsigned)n && (unsigned)c < (unsigned)n)
        atomicAdd(&g_deg[c], 1);
}

// single-block exclusive scan over deg -> rowptr (also fills cursor)
__global__ void k_scan(int n) {
    __shared__ int sh[1024];
    int t = threadIdx.x;
    int chunk = (n + 1023) >> 10;
    int beg = t * chunk;
    int end = beg + chunk; if (end > n) end = n;
    int sum = 0;
    for (int i = beg; i < end; ++i) sum += g_deg[i];
    sh[t] = sum;
    __syncthreads();
    for (int off = 1; off < 1024; off <<= 1) {
        int v = (t >= off) ? sh[t - off] : 0;
        __syncthreads();
        sh[t] += v;
        __syncthreads();
    }
    int run = (t > 0) ? sh[t - 1] : 0;
    for (int i = beg; i < end; ++i) {
        g_rowptr[i] = run;
        g_cursor[i] = run;
        run += g_deg[i];
    }
    if (t == 1023) g_rowptr[n] = sh[1023];
}

__global__ void k_dis(int n) {
    int i = blockIdx.x * blockDim.x + threadIdx.x;
    if (i >= n) return;
    int d = g_deg[i];
    g_dis[i]  = (d > 0) ? rsqrtf((float)d) : 0.f;
    g_dis2[i] = rsqrtf((float)d + 1.f);
}

__global__ void k_scatter(const int* __restrict__ ei32, int e_cnt, int n) {
    int e = blockIdx.x * blockDim.x + threadIdx.x;
    if (e >= e_cnt) return;
    int r = load_row(ei32, e_cnt, e);
    int c = load_col(ei32, e_cnt, e);
    if ((unsigned)r >= (unsigned)n || (unsigned)c >= (unsigned)n) return;
    int pos = atomicAdd(&g_cursor[c], 1);
    g_srcs[pos] = r;
    g_wtag[pos] = g_dis[r]  * g_dis[c];
    g_wgcn[pos] = g_dis2[r] * g_dis2[c];
}

// ---------------- propagation: hout[n][c] = sum_e w[e] * hin[src[e]][c] ----------------
// hinSel == SEL_EXT -> use hin_ext.  wSel: 0 -> g_wtag, 1 -> g_wgcn.
__global__ void k_prop(const float* __restrict__ hin_ext, int hinSel, int houtSel,
                       int wSel, int C, int n) {
    const float* hin = (hinSel == SEL_EXT) ? hin_ext : selbuf(hinSel);
    float* hout = selbuf(houtSel);
    const float* w = (wSel == 0) ? g_wtag : g_wgcn;
    int node = blockIdx.x * blockDim.y + threadIdx.y;
    int c = threadIdx.x;
    if (node >= n || c >= C) return;
    int beg = g_rowptr[node], end = g_rowptr[node + 1];
    float a0 = 0.f, a1 = 0.f;
    int e = beg;
    for (; e + 1 < end; e += 2) {
        int s0 = g_srcs[e], s1 = g_srcs[e + 1];
        float w0 = w[e], w1 = w[e + 1];
        a0 += w0 * hin[s0 * C + c];
        a1 += w1 * hin[s1 * C + c];
    }
    if (e < end) a0 += w[e] * hin[g_srcs[e] * C + c];
    hout[node * C + c] = a0 + a1;
}

// ---------------- fused multi-hop matmul ----------------
// out[row][c] = act( sum_{k<nK} h_k[row] @ W[k] + bias )
// Block: 256 threads = 8 warps, each warp owns 4 rows; W staged in smem.
__global__ void k_mm(const float* __restrict__ h_ext,
                     int s0, int s1, int s2, int s3,
                     const float* __restrict__ W_ext, int Wsel,
                     const float* __restrict__ bias,
                     int outSel, int n, int Cin, int Cout,
                     int nK, int doRelu) {
    extern __shared__ float smem[];
    float* Wst = smem;                        // Cin*Cout (+32 pad for OOB-safe reads)
    float* Rst = smem + Cin * Cout + 32;      // 32 rows * Cin
    const float* W = (Wsel == 1) ? g_Wc : W_ext;
    float* out = selbuf(outSel);
    int lane = threadIdx.x & 31;
    int wid  = threadIdx.x >> 5;
    int rowBase = blockIdx.x * 32 + wid * 4;
    int sels[4] = {s0, s1, s2, s3};
    int nj = (Cout + 31) >> 5;                // accumulator columns per lane
    float acc[4][3];
#pragma unroll
    for (int r = 0; r < 4; ++r) { acc[r][0] = 0.f; acc[r][1] = 0.f; acc[r][2] = 0.f; }

    for (int k = 0; k < nK; ++k) {
        __syncthreads();
        for (int i = threadIdx.x; i < Cin * Cout; i += blockDim.x)
            Wst[i] = W[k * Cin * Cout + i];
        const float* hk = (sels[k] == SEL_EXT) ? h_ext : selbuf(sels[k]);
#pragma unroll
        for (int r = 0; r < 4; ++r) {
            int row = rowBase + r;
            float* dst = &Rst[(wid * 4 + r) * Cin];
            if (row < n) {
                for (int i = lane; i < Cin; i += 32) dst[i] = hk[row * Cin + i];
            } else {
                for (int i = lane; i < Cin; i += 32) dst[i] = 0.f;
            }
        }
        __syncthreads();
        for (int kin = 0; kin < Cin; ++kin) {
            float x0 = Rst[(wid * 4 + 0) * Cin + kin];
            float x1 = Rst[(wid * 4 + 1) * Cin + kin];
            float x2 = Rst[(wid * 4 + 2) * Cin + kin];
            float x3 = Rst[(wid * 4 + 3) * Cin + kin];
            const float* wrow = &Wst[kin * Cout + lane];
#pragma unroll
            for (int j = 0; j < 3; ++j) {
                if (j < nj) {
                    float wv = wrow[32 * j];   // dead lanes may read padded garbage; never stored
                    acc[0][j] += x0 * wv;
                    acc[1][j] += x1 * wv;
                    acc[2][j] += x2 * wv;
                    acc[3][j] += x3 * wv;
                }
            }
        }
    }
#pragma unroll
    for (int r = 0; r < 4; ++r) {
        int row = rowBase + r;
        if (row >= n) continue;
        for (int j = 0; j < nj; ++j) {
            int cc = lane + 32 * j;
            if (cc < Cout) {
                float v = acc[r][j];
                if (bias) v += bias[cc];
                if (doRelu) v = fmaxf(v, 0.f);
                out[row * Cout + cc] = v;
            }
        }
    }
}

// pack [Wmu | Wls] -> g_Wc[Cin=43][32]
__global__ void k_packw(const float* __restrict__ Wmu, const float* __restrict__ Wls) {
    int i = blockIdx.x * blockDim.x + threadIdx.x;
    if (i >= C2 * 2 * CO) return;
    int kin = i / (2 * CO), c = i % (2 * CO);
    g_Wc[i] = (c < CO) ? Wmu[kin * CO + c] : Wls[kin * CO + (c - CO)];
}

// out = agg + dis2^2 * y + bias, split into mu / logstd halves
__global__ void k_final(const float* __restrict__ bmu, const float* __restrict__ bls,
                        float* __restrict__ outmu, float* __restrict__ outls, int n) {
    int i = blockIdx.x * blockDim.x + threadIdx.x;
    if (i >= n * CO) return;
    int node = i >> 4, c = i & 15;
    float d2 = g_dis2[node];
    float s = d2 * d2;
    outmu[i] = g_agg[node * 32 + c]      + s * g_y[node * 32 + c]      + bmu[c];
    outls[i] = g_agg[node * 32 + 16 + c] + s * g_y[node * 32 + 16 + c] + bls[c];
}

// ---------------- host launch ----------------
extern "C" void kernel_launch(void* const* d_in, const int* in_sizes, int n_in,
                              void* d_out, int out_size) {
    (void)n_in; (void)out_size;
    const float* x    = (const float*)d_in[0];
    const int*   ei32 = (const int*)d_in[1];   // int32 words; layout auto-detected
    const float* W1   = (const float*)d_in[2];
    const float* b1   = (const float*)d_in[3];
    const float* W2   = (const float*)d_in[4];
    const float* b2   = (const float*)d_in[5];
    const float* Wmu  = (const float*)d_in[6];
    const float* bmu  = (const float*)d_in[7];
    const float* Wls  = (const float*)d_in[8];
    const float* bls  = (const float*)d_in[9];
    float* out = (float*)d_out;

    int n = in_sizes[0] / C0;   // 50000
    int e = in_sizes[1] / 2;    // 800000 (element count is dtype-agnostic)

    // --- graph structure ---
    k_detect<<<1, 256>>>(ei32);
    k_zero_deg<<<(n + 255) / 256, 256>>>(n);
    k_hist<<<(e + 255) / 256, 256>>>(ei32, e, n);
    k_scan<<<1, 1024>>>(n);
    k_dis<<<(n + 255) / 256, 256>>>(n);
    k_scatter<<<(e + 255) / 256, 256>>>(ei32, e, n);

    // --- TAG layer 1 (C=96 -> 70) ---
    {
        dim3 blk(C0, 4);
        int grid = (n + 3) / 4;
        k_prop<<<grid, blk>>>(x, SEL_EXT, SEL_A, 0, C0, n);
        k_prop<<<grid, blk>>>(0, SEL_A,   SEL_B, 0, C0, n);
        k_prop<<<grid, blk>>>(0, SEL_B,   SEL_C, 0, C0, n);
        size_t sm = (size_t)(C0 * C1 + 32 + 32 * C0) * sizeof(float);
        k_mm<<<(n + 31) / 32, 256, sm>>>(x, SEL_EXT, SEL_A, SEL_B, SEL_C,
                                         W1, 0, b1, SEL_L1, n, C0, C1, 4, 1);
    }

    // --- TAG layer 2 (C=70 -> 43) ---
    {
        dim3 blk(C1, 4);
        int grid = (n + 3) / 4;
        k_prop<<<grid, blk>>>(0, SEL_L1, SEL_A, 0, C1, n);
        k_prop<<<grid, blk>>>(0, SEL_A,  SEL_B, 0, C1, n);
        k_prop<<<grid, blk>>>(0, SEL_B,  SEL_C, 0, C1, n);
        size_t sm = (size_t)(C1 * C2 + 32 + 32 * C1) * sizeof(float);
        k_mm<<<(n + 31) / 32, 256, sm>>>(0, SEL_L1, SEL_A, SEL_B, SEL_C,
                                         W2, 0, b2, SEL_L2, n, C1, C2, 4, 1);
    }

    // --- dual GCN head (fused mu+logstd, C=43 -> 32) ---
    {
        k_packw<<<(C2 * 2 * CO + 255) / 256, 256>>>(Wmu, Wls);
        size_t sm = (size_t)(C2 * 2 * CO + 32 + 32 * C2) * sizeof(float);
        k_mm<<<(n + 31) / 32, 256, sm>>>(0, SEL_L2, SEL_L2, SEL_L2, SEL_L2,
                                         0, 1, (const float*)0, SEL_Y,
                                         n, C2, 2 * CO, 1, 0);
        dim3 blk(2 * CO, 8);
        k_prop<<<(n + 7) / 8, blk>>>(0, SEL_Y, SEL_AGG, 1, 2 * CO, n);
        k_final<<<(n * CO + 255) / 256, 256>>>(bmu, bls, out, out + (size_t)n * CO, n);
    }
}

// round 11
// speedup vs baseline: 1.2775x; 1.2775x over previous
#include <cuda_runtime.h>

// Problem constants (fixed by the dataset)
#define NN 50000
#define EE 800000
#define C0 96   // input channels
#define C1 70   // layer-1 out
#define C2 43   // layer-2 out
#define CO 16   // mu / logstd channels

#define SCAN_T 256
#define SCAN_NB ((NN + SCAN_T - 1) / SCAN_T)   // 196

// ---------------- scratch (static __device__ arrays; no allocations) ----------------
__device__ int   g_is64;          // 1 if edge_index buffer is int64 words
__device__ int   g_deg[NN];
__device__ float g_dis[NN];
__device__ float g_dis2[NN];
__device__ int   g_rowptr[NN + 1];
__device__ int   g_cursor[NN];
__device__ int   g_blkinc[SCAN_NB];   // inclusive scan of per-block sums
__device__ int   g_srcs[EE];
__device__ float g_wtag[EE];
__device__ float g_wgcn[EE];
__device__ float g_bufA[NN * C0];   // reused: 96-ch and 70-ch hops
__device__ float g_bufB[NN * C0];
__device__ float g_bufC[NN * C0];
__device__ float g_l1out[NN * C1];
__device__ float g_l2out[NN * C2];
__device__ float g_y[NN * 2 * CO];
__device__ float g_agg[NN * 2 * CO];
__device__ float g_Wc[C2 * 2 * CO];

// Buffer selectors: device code resolves ints -> __device__ globals, so the
// host never touches symbol addresses.
#define SEL_A    0
#define SEL_B    1
#define SEL_C    2
#define SEL_L1   3
#define SEL_L2   4
#define SEL_Y    5
#define SEL_AGG  6
#define SEL_EXT  (-1)

__device__ __forceinline__ float* selbuf(int s) {
    switch (s) {
        case SEL_A:   return g_bufA;
        case SEL_B:   return g_bufB;
        case SEL_C:   return g_bufC;
        case SEL_L1:  return g_l1out;
        case SEL_L2:  return g_l2out;
        case SEL_Y:   return g_y;
        case SEL_AGG: return g_agg;
    }
    return 0;
}

// row / col index of edge e under either word layout
__device__ __forceinline__ int load_row(const int* ei32, int e_cnt, int e) {
    return g_is64 ? ei32[2 * (long long)e] : ei32[e];
}
__device__ __forceinline__ int load_col(const int* ei32, int e_cnt, int e) {
    return g_is64 ? ei32[2 * ((long long)e_cnt + e)] : ei32[e_cnt + e];
}

// ---------------- dtype detection ----------------
__global__ void k_detect(const int* __restrict__ ei32) {
    __shared__ int any;
    if (threadIdx.x == 0) any = 0;
    __syncthreads();
    int local = 0;
    for (int i = threadIdx.x; i < 4096; i += blockDim.x)
        if (ei32[2 * i + 1] != 0) local = 1;
    if (local) atomicOr(&any, 1);
    __syncthreads();
    if (threadIdx.x == 0) g_is64 = (any == 0) ? 1 : 0;
}

// ---------------- graph-structure kernels ----------------
__global__ void k_zero_deg(int n) {
    int i = blockIdx.x * blockDim.x + threadIdx.x;
    if (i < n) g_deg[i] = 0;
}

__global__ void k_hist(const int* __restrict__ ei32, int e_cnt, int n) {
    int e = blockIdx.x * blockDim.x + threadIdx.x;
    if (e >= e_cnt) return;
    int r = load_row(ei32, e_cnt, e);
    int c = load_col(ei32, e_cnt, e);
    if ((unsigned)r < (unsigned)n && (unsigned)c < (unsigned)n)
        atomicAdd(&g_deg[c], 1);
}

// --- decoupled 3-phase scan ---
// phase 1: per-block sums of deg
__global__ void k_scan1(int n) {
    __shared__ int sh[SCAN_T];
    int i = blockIdx.x * SCAN_T + threadIdx.x;
    int v = (i < n) ? g_deg[i] : 0;
    sh[threadIdx.x] = v;
    __syncthreads();
    for (int off = SCAN_T / 2; off > 0; off >>= 1) {
        if (threadIdx.x < off) sh[threadIdx.x] += sh[threadIdx.x + off];
        __syncthreads();
    }
    if (threadIdx.x == 0) g_blkinc[blockIdx.x] = sh[0];
}
// phase 2: single-block inclusive scan over SCAN_NB block sums
__global__ void k_scan2(int nb) {
    __shared__ int sh[SCAN_T];
    int t = threadIdx.x;
    int v = (t < nb) ? g_blkinc[t] : 0;
    sh[t] = v;
    __syncthreads();
    for (int off = 1; off < SCAN_T; off <<= 1) {
        int u = (t >= off) ? sh[t - off] : 0;
        __syncthreads();
        sh[t] += u;
        __syncthreads();
    }
    if (t < nb) g_blkinc[t] = sh[t];
}
// phase 3: per-block exclusive scan + offsets -> rowptr/cursor; also dis/dis2
__global__ void k_scan3(int n, int nb) {
    __shared__ int sh[SCAN_T];
    int t = threadIdx.x;
    int i = blockIdx.x * SCAN_T + t;
    int v = (i < n) ? g_deg[i] : 0;
    sh[t] = v;
    __syncthreads();
    for (int off = 1; off < SCAN_T; off <<= 1) {
        int u = (t >= off) ? sh[t - off] : 0;
        __syncthreads();
        sh[t] += u;
        __syncthreads();
    }
    int blkoff = (blockIdx.x > 0) ? g_blkinc[blockIdx.x - 1] : 0;
    if (i < n) {
        int ex = blkoff + sh[t] - v;    // exclusive
        g_rowptr[i] = ex;
        g_cursor[i] = ex;
        g_dis[i]  = (v > 0) ? rsqrtf((float)v) : 0.f;
        g_dis2[i] = rsqrtf((float)v + 1.f);
    }
    if (blockIdx.x == nb - 1 && t == 0) g_rowptr[n] = g_blkinc[nb - 1];
}

__global__ void k_scatter(const int* __restrict__ ei32, int e_cnt, int n) {
    int e = blockIdx.x * blockDim.x + threadIdx.x;
    if (e >= e_cnt) return;
    int r = load_row(ei32, e_cnt, e);
    int c = load_col(ei32, e_cnt, e);
    if ((unsigned)r >= (unsigned)n || (unsigned)c >= (unsigned)n) return;
    int pos = atomicAdd(&g_cursor[c], 1);
    g_srcs[pos] = r;
    g_wtag[pos] = g_dis[r]  * g_dis[c];
    g_wgcn[pos] = g_dis2[r] * g_dis2[c];
}

// ---------------- propagation (float2-vectorized) ----------------
// hout[n][c] = sum_e w[e] * hin[src[e]][c]; each thread owns 2 channels.
// Cv = C/2. hinSel == SEL_EXT -> hin_ext. wSel: 0 -> g_wtag, 1 -> g_wgcn.
__global__ void k_prop(const float* __restrict__ hin_ext, int hinSel, int houtSel,
                       int wSel, int Cv, int n) {
    const float2* hin = (const float2*)((hinSel == SEL_EXT) ? hin_ext : selbuf(hinSel));
    float2* hout = (float2*)selbuf(houtSel);
    const float* __restrict__ w = (wSel == 0) ? g_wtag : g_wgcn;
    int node = blockIdx.x * blockDim.y + threadIdx.y;
    int c = threadIdx.x;
    if (node >= n) return;
    int beg = g_rowptr[node], end = g_rowptr[node + 1];
    float ax0 = 0.f, ay0 = 0.f, ax1 = 0.f, ay1 = 0.f;
    int e = beg;
    for (; e + 1 < end; e += 2) {
        int s0 = g_srcs[e], s1 = g_srcs[e + 1];
        float w0 = w[e], w1 = w[e + 1];
        float2 v0 = hin[(long long)s0 * Cv + c];
        float2 v1 = hin[(long long)s1 * Cv + c];
        ax0 += w0 * v0.x; ay0 += w0 * v0.y;
        ax1 += w1 * v1.x; ay1 += w1 * v1.y;
    }
    if (e < end) {
        float we = w[e];
        float2 v = hin[(long long)g_srcs[e] * Cv + c];
        ax0 += we * v.x; ay0 += we * v.y;
    }
    float2 r; r.x = ax0 + ax1; r.y = ay0 + ay1;
    hout[(long long)node * Cv + c] = r;
}

// ---------------- fused multi-hop matmul ----------------
// out[row][c] = act( sum_{k<nK} h_k[row] @ W[k] + bias )
// Block: 256 threads = 8 warps, each warp owns 4 rows; W staged in smem.
__global__ void k_mm(const float* __restrict__ h_ext,
                     int s0, int s1, int s2, int s3,
                     const float* __restrict__ W_ext, int Wsel,
                     const float* __restrict__ bias,
                     int outSel, int n, int Cin, int Cout,
                     int nK, int doRelu) {
    extern __shared__ float smem[];
    float* Wst = smem;                        // Cin*Cout (+32 pad for OOB-safe reads)
    float* Rst = smem + Cin * Cout + 32;      // 32 rows * Cin
    const float* W = (Wsel == 1) ? g_Wc : W_ext;
    float* out = selbuf(outSel);
    int lane = threadIdx.x & 31;
    int wid  = threadIdx.x >> 5;
    int rowBase = blockIdx.x * 32 + wid * 4;
    int sels[4] = {s0, s1, s2, s3};
    int nj = (Cout + 31) >> 5;                // accumulator columns per lane
    float acc[4][3];
#pragma unroll
    for (int r = 0; r < 4; ++r) { acc[r][0] = 0.f; acc[r][1] = 0.f; acc[r][2] = 0.f; }

    for (int k = 0; k < nK; ++k) {
        __syncthreads();
        for (int i = threadIdx.x; i < Cin * Cout; i += blockDim.x)
            Wst[i] = W[k * Cin * Cout + i];
        const float* hk = (sels[k] == SEL_EXT) ? h_ext : selbuf(sels[k]);
#pragma unroll
        for (int r = 0; r < 4; ++r) {
            int row = rowBase + r;
            float* dst = &Rst[(wid * 4 + r) * Cin];
            if (row < n) {
                for (int i = lane; i < Cin; i += 32) dst[i] = hk[(long long)row * Cin + i];
            } else {
                for (int i = lane; i < Cin; i += 32) dst[i] = 0.f;
            }
        }
        __syncthreads();
        for (int kin = 0; kin < Cin; ++kin) {
            float x0 = Rst[(wid * 4 + 0) * Cin + kin];
            float x1 = Rst[(wid * 4 + 1) * Cin + kin];
            float x2 = Rst[(wid * 4 + 2) * Cin + kin];
            float x3 = Rst[(wid * 4 + 3) * Cin + kin];
            const float* wrow = &Wst[kin * Cout + lane];
#pragma unroll
            for (int j = 0; j < 3; ++j) {
                if (j < nj) {
                    float wv = wrow[32 * j];   // dead lanes may read padded garbage; never stored
                    acc[0][j] += x0 * wv;
                    acc[1][j] += x1 * wv;
                    acc[2][j] += x2 * wv;
                    acc[3][j] += x3 * wv;
                }
            }
        }
    }
#pragma unroll
    for (int r = 0; r < 4; ++r) {
        int row = rowBase + r;
        if (row >= n) continue;
        for (int j = 0; j < nj; ++j) {
            int cc = lane + 32 * j;
            if (cc < Cout) {
                float v = acc[r][j];
                if (bias) v += bias[cc];
                if (doRelu) v = fmaxf(v, 0.f);
                out[(long long)row * Cout + cc] = v;
            }
        }
    }
}

// pack [Wmu | Wls] -> g_Wc[Cin=43][32]
__global__ void k_packw(const float* __restrict__ Wmu, const float* __restrict__ Wls) {
    int i = blockIdx.x * blockDim.x + threadIdx.x;
    if (i >= C2 * 2 * CO) return;
    int kin = i / (2 * CO), c = i % (2 * CO);
    g_Wc[i] = (c < CO) ? Wmu[kin * CO + c] : Wls[kin * CO + (c - CO)];
}

// out = agg + dis2^2 * y + bias, split into mu / logstd halves
__global__ void k_final(const float* __restrict__ bmu, const float* __restrict__ bls,
                        float* __restrict__ outmu, float* __restrict__ outls, int n) {
    int i = blockIdx.x * blockDim.x + threadIdx.x;
    if (i >= n * CO) return;
    int node = i >> 4, c = i & 15;
    float d2 = g_dis2[node];
    float s = d2 * d2;
    outmu[i] = g_agg[node * 32 + c]      + s * g_y[node * 32 + c]      + bmu[c];
    outls[i] = g_agg[node * 32 + 16 + c] + s * g_y[node * 32 + 16 + c] + bls[c];
}

// ---------------- host launch ----------------
extern "C" void kernel_launch(void* const* d_in, const int* in_sizes, int n_in,
                              void* d_out, int out_size) {
    (void)n_in; (void)out_size;
    const float* x    = (const float*)d_in[0];
    const int*   ei32 = (const int*)d_in[1];   // int32 words; layout auto-detected
    const float* W1   = (const float*)d_in[2];
    const float* b1   = (const float*)d_in[3];
    const float* W2   = (const float*)d_in[4];
    const float* b2   = (const float*)d_in[5];
    const float* Wmu  = (const float*)d_in[6];
    const float* bmu  = (const float*)d_in[7];
    const float* Wls  = (const float*)d_in[8];
    const float* bls  = (const float*)d_in[9];
    float* out = (float*)d_out;

    int n = in_sizes[0] / C0;   // 50000
    int e = in_sizes[1] / 2;    // 800000 (element count is dtype-agnostic)
    int nb = (n + SCAN_T - 1) / SCAN_T;

    // --- graph structure ---
    k_detect<<<1, 256>>>(ei32);
    k_zero_deg<<<(n + 255) / 256, 256>>>(n);
    k_hist<<<(e + 255) / 256, 256>>>(ei32, e, n);
    k_scan1<<<nb, SCAN_T>>>(n);
    k_scan2<<<1, SCAN_T>>>(nb);
    k_scan3<<<nb, SCAN_T>>>(n, nb);
    k_scatter<<<(e + 255) / 256, 256>>>(ei32, e, n);

    // --- TAG layer 1 (C=96 -> 70) ---
    {
        dim3 blk(C0 / 2, 8);
        int grid = (n + 7) / 8;
        k_prop<<<grid, blk>>>(x, SEL_EXT, SEL_A, 0, C0 / 2, n);
        k_prop<<<grid, blk>>>(0, SEL_A,   SEL_B, 0, C0 / 2, n);
        k_prop<<<grid, blk>>>(0, SEL_B,   SEL_C, 0, C0 / 2, n);
        size_t sm = (size_t)(C0 * C1 + 32 + 32 * C0) * sizeof(float);
        k_mm<<<(n + 31) / 32, 256, sm>>>(x, SEL_EXT, SEL_A, SEL_B, SEL_C,
                                         W1, 0, b1, SEL_L1, n, C0, C1, 4, 1);
    }

    // --- TAG layer 2 (C=70 -> 43) ---
    {
        dim3 blk(C1 / 2, 8);
        int grid = (n + 7) / 8;
        k_prop<<<grid, blk>>>(0, SEL_L1, SEL_A, 0, C1 / 2, n);
        k_prop<<<grid, blk>>>(0, SEL_A,  SEL_B, 0, C1 / 2, n);
        k_prop<<<grid, blk>>>(0, SEL_B,  SEL_C, 0, C1 / 2, n);
        size_t sm = (size_t)(C1 * C2 + 32 + 32 * C1) * sizeof(float);
        k_mm<<<(n + 31) / 32, 256, sm>>>(0, SEL_L1, SEL_A, SEL_B, SEL_C,
                                         W2, 0, b2, SEL_L2, n, C1, C2, 4, 1);
    }

    // --- dual GCN head (fused mu+logstd, C=43 -> 32) ---
    {
        k_packw<<<(C2 * 2 * CO + 255) / 256, 256>>>(Wmu, Wls);
        size_t sm = (size_t)(C2 * 2 * CO + 32 + 32 * C2) * sizeof(float);
        k_mm<<<(n + 31) / 32, 256, sm>>>(0, SEL_L2, SEL_L2, SEL_L2, SEL_L2,
                                         0, 1, (const float*)0, SEL_Y,
                                         n, C2, 2 * CO, 1, 0);
        dim3 blk(CO, 16);   // 16 float2 lanes = 32 channels
        k_prop<<<(n + 15) / 16, blk>>>(0, SEL_Y, SEL_AGG, 1, CO, n);
        k_final<<<(n * CO + 255) / 256, 256>>>(bmu, bls, out, out + (size_t)n * CO, n);
    }
}

// round 12
// speedup vs baseline: 1.2858x; 1.0065x over previous
#include <cuda_runtime.h>

// Problem constants (fixed by the dataset)
#define NN 50000
#define EE 800000
#define C0 96   // input channels
#define C1 70   // layer-1 out
#define C2 43   // layer-2 out
#define CO 16   // mu / logstd channels

#define SCAN_T 256
#define SCAN_NB ((NN + SCAN_T - 1) / SCAN_T)   // 196

// ---------------- scratch (static __device__ arrays; no allocations) ----------------
__device__ int   g_is64;          // 1 if edge_index buffer is int64 words
__device__ int   g_deg[NN];
__device__ float g_dis[NN];
__device__ float g_dis2[NN];
__device__ int   g_rowptr[NN + 1];
__device__ int   g_cursor[NN];
__device__ int   g_blkinc[SCAN_NB];   // inclusive scan of per-block sums
__device__ int   g_srcs[EE];
__device__ float g_wtag[EE];
__device__ float g_wgcn[EE];
__device__ float g_bufA[NN * C0];   // reused: 96-ch and 70-ch hops
__device__ float g_bufB[NN * C0];
__device__ float g_bufC[NN * C0];
__device__ float g_l1out[NN * C1];
__device__ float g_l2out[NN * C2];
__device__ float g_y[NN * 2 * CO];
__device__ float g_agg[NN * 2 * CO];
__device__ float g_Wc[C2 * 2 * CO];

// Buffer selectors (device-resolved; host never touches symbol addresses).
#define SEL_A    0
#define SEL_B    1
#define SEL_C    2
#define SEL_L1   3
#define SEL_L2   4
#define SEL_Y    5
#define SEL_AGG  6
#define SEL_EXT  (-1)

__device__ __forceinline__ float* selbuf(int s) {
    switch (s) {
        case SEL_A:   return g_bufA;
        case SEL_B:   return g_bufB;
        case SEL_C:   return g_bufC;
        case SEL_L1:  return g_l1out;
        case SEL_L2:  return g_l2out;
        case SEL_Y:   return g_y;
        case SEL_AGG: return g_agg;
    }
    return 0;
}

// row / col index of edge e under either word layout
__device__ __forceinline__ int load_row(const int* ei32, int e_cnt, int e) {
    return g_is64 ? ei32[2 * (long long)e] : ei32[e];
}
__device__ __forceinline__ int load_col(const int* ei32, int e_cnt, int e) {
    return g_is64 ? ei32[2 * ((long long)e_cnt + e)] : ei32[e_cnt + e];
}

// ---------------- dtype detection ----------------
__global__ void k_detect(const int* __restrict__ ei32) {
    __shared__ int any;
    if (threadIdx.x == 0) any = 0;
    __syncthreads();
    int local = 0;
    for (int i = threadIdx.x; i < 4096; i += blockDim.x)
        if (ei32[2 * i + 1] != 0) local = 1;
    if (local) atomicOr(&any, 1);
    __syncthreads();
    if (threadIdx.x == 0) g_is64 = (any == 0) ? 1 : 0;
}

// ---------------- graph-structure kernels ----------------
__global__ void k_zero_deg(int n) {
    int i = blockIdx.x * blockDim.x + threadIdx.x;
    if (i < n) g_deg[i] = 0;
}

__global__ void k_hist(const int* __restrict__ ei32, int e_cnt, int n) {
    int e = blockIdx.x * blockDim.x + threadIdx.x;
    if (e >= e_cnt) return;
    int r = load_row(ei32, e_cnt, e);
    int c = load_col(ei32, e_cnt, e);
    if ((unsigned)r < (unsigned)n && (unsigned)c < (unsigned)n)
        atomicAdd(&g_deg[c], 1);
}

// --- decoupled 3-phase scan ---
__global__ void k_scan1(int n) {
    __shared__ int sh[SCAN_T];
    int i = blockIdx.x * SCAN_T + threadIdx.x;
    int v = (i < n) ? g_deg[i] : 0;
    sh[threadIdx.x] = v;
    __syncthreads();
    for (int off = SCAN_T / 2; off > 0; off >>= 1) {
        if (threadIdx.x < off) sh[threadIdx.x] += sh[threadIdx.x + off];
        __syncthreads();
    }
    if (threadIdx.x == 0) g_blkinc[blockIdx.x] = sh[0];
}
__global__ void k_scan2(int nb) {
    __shared__ int sh[SCAN_T];
    int t = threadIdx.x;
    int v = (t < nb) ? g_blkinc[t] : 0;
    sh[t] = v;
    __syncthreads();
    for (int off = 1; off < SCAN_T; off <<= 1) {
        int u = (t >= off) ? sh[t - off] : 0;
        __syncthreads();
        sh[t] += u;
        __syncthreads();
    }
    if (t < nb) g_blkinc[t] = sh[t];
}
__global__ void k_scan3(int n, int nb) {
    __shared__ int sh[SCAN_T];
    int t = threadIdx.x;
    int i = blockIdx.x * SCAN_T + t;
    int v = (i < n) ? g_deg[i] : 0;
    sh[t] = v;
    __syncthreads();
    for (int off = 1; off < SCAN_T; off <<= 1) {
        int u = (t >= off) ? sh[t - off] : 0;
        __syncthreads();
        sh[t] += u;
        __syncthreads();
    }
    int blkoff = (blockIdx.x > 0) ? g_blkinc[blockIdx.x - 1] : 0;
    if (i < n) {
        int ex = blkoff + sh[t] - v;    // exclusive
        g_rowptr[i] = ex;
        g_cursor[i] = ex;
        g_dis[i]  = (v > 0) ? rsqrtf((float)v) : 0.f;
        g_dis2[i] = rsqrtf((float)v + 1.f);
    }
    if (blockIdx.x == nb - 1 && t == 0) g_rowptr[n] = g_blkinc[nb - 1];
}

__global__ void k_scatter(const int* __restrict__ ei32, int e_cnt, int n) {
    int e = blockIdx.x * blockDim.x + threadIdx.x;
    if (e >= e_cnt) return;
    int r = load_row(ei32, e_cnt, e);
    int c = load_col(ei32, e_cnt, e);
    if ((unsigned)r >= (unsigned)n || (unsigned)c >= (unsigned)n) return;
    int pos = atomicAdd(&g_cursor[c], 1);
    g_srcs[pos] = r;
    g_wtag[pos] = g_dis[r]  * g_dis[c];
    g_wgcn[pos] = g_dis2[r] * g_dis2[c];
}

// ---------------- propagation: warp-per-node, float2 channel slots ----------------
// hout[n][c] = sum_e w[e] * hin[src[e]][c].
// blockDim = (32, WPB). Each warp owns ONE node; lane owns float2 slots
// {lane, lane+32} (predication fixed per lane -> zero loop divergence).
// Cv = C/2 (<= 64). wSel: 0 -> g_wtag, 1 -> g_wgcn.
__global__ void k_prop(const float* __restrict__ hin_ext, int hinSel, int houtSel,
                       int wSel, int Cv, int n) {
    const float2* __restrict__ hin =
        (const float2*)((hinSel == SEL_EXT) ? hin_ext : selbuf(hinSel));
    float2* hout = (float2*)selbuf(houtSel);
    const float* __restrict__ w = (wSel == 0) ? g_wtag : g_wgcn;
    int node = blockIdx.x * blockDim.y + threadIdx.y;
    if (node >= n) return;
    int lane = threadIdx.x;
    int c0 = lane, c1 = lane + 32;
    bool h1 = (c1 < Cv);
    bool h0 = (c0 < Cv);
    int beg = g_rowptr[node], end = g_rowptr[node + 1];

    float ax0 = 0.f, ay0 = 0.f, ax1 = 0.f, ay1 = 0.f;   // slot c0, edges even/odd
    float bx0 = 0.f, by0 = 0.f, bx1 = 0.f, by1 = 0.f;   // slot c1
    int e = beg;
    for (; e + 1 < end; e += 2) {
        int s0 = g_srcs[e], s1 = g_srcs[e + 1];          // warp-uniform broadcast
        float w0 = w[e], w1 = w[e + 1];
        long long r0 = (long long)s0 * Cv, r1 = (long long)s1 * Cv;
        if (h0) {
            float2 v0 = hin[r0 + c0]; ax0 += w0 * v0.x; ay0 += w0 * v0.y;
            float2 v1 = hin[r1 + c0]; ax1 += w1 * v1.x; ay1 += w1 * v1.y;
        }
        if (h1) {
            float2 u0 = hin[r0 + c1]; bx0 += w0 * u0.x; by0 += w0 * u0.y;
            float2 u1 = hin[r1 + c1]; bx1 += w1 * u1.x; by1 += w1 * u1.y;
        }
    }
    if (e < end) {
        int s = g_srcs[e];
        float we = w[e];
        long long r = (long long)s * Cv;
        if (h0) { float2 v = hin[r + c0]; ax0 += we * v.x; ay0 += we * v.y; }
        if (h1) { float2 u = hin[r + c1]; bx0 += we * u.x; by0 += we * u.y; }
    }
    long long o = (long long)node * Cv;
    if (h0) { float2 r; r.x = ax0 + ax1; r.y = ay0 + ay1; hout[o + c0] = r; }
    if (h1) { float2 r; r.x = bx0 + bx1; r.y = by0 + by1; hout[o + c1] = r; }
}

// ---------------- fused multi-hop matmul ----------------
// out[row][c] = act( sum_{k<nK} h_k[row] @ W[k] + bias )
// Block: 256 threads = 8 warps, each warp owns 4 rows; W staged in smem.
__global__ void k_mm(const float* __restrict__ h_ext,
                     int s0, int s1, int s2, int s3,
                     const float* __restrict__ W_ext, int Wsel,
                     const float* __restrict__ bias,
                     int outSel, int n, int Cin, int Cout,
                     int nK, int doRelu) {
    extern __shared__ float smem[];
    float* Wst = smem;                        // Cin*Cout (+32 pad for OOB-safe reads)
    float* Rst = smem + Cin * Cout + 32;      // 32 rows * Cin
    const float* W = (Wsel == 1) ? g_Wc : W_ext;
    float* out = selbuf(outSel);
    int lane = threadIdx.x & 31;
    int wid  = threadIdx.x >> 5;
    int rowBase = blockIdx.x * 32 + wid * 4;
    int sels[4] = {s0, s1, s2, s3};
    int nj = (Cout + 31) >> 5;                // accumulator columns per lane
    float acc[4][3];
#pragma unroll
    for (int r = 0; r < 4; ++r) { acc[r][0] = 0.f; acc[r][1] = 0.f; acc[r][2] = 0.f; }

    for (int k = 0; k < nK; ++k) {
        __syncthreads();
        for (int i = threadIdx.x; i < Cin * Cout; i += blockDim.x)
            Wst[i] = W[k * Cin * Cout + i];
        const float* hk = (sels[k] == SEL_EXT) ? h_ext : selbuf(sels[k]);
#pragma unroll
        for (int r = 0; r < 4; ++r) {
            int row = rowBase + r;
            float* dst = &Rst[(wid * 4 + r) * Cin];
            if (row < n) {
                for (int i = lane; i < Cin; i += 32) dst[i] = hk[(long long)row * Cin + i];
            } else {
                for (int i = lane; i < Cin; i += 32) dst[i] = 0.f;
            }
        }
        __syncthreads();
        for (int kin = 0; kin < Cin; ++kin) {
            float x0 = Rst[(wid * 4 + 0) * Cin + kin];
            float x1 = Rst[(wid * 4 + 1) * Cin + kin];
            float x2 = Rst[(wid * 4 + 2) * Cin + kin];
            float x3 = Rst[(wid * 4 + 3) * Cin + kin];
            const float* wrow = &Wst[kin * Cout + lane];
#pragma unroll
            for (int j = 0; j < 3; ++j) {
                if (j < nj) {
                    float wv = wrow[32 * j];   // dead lanes may read padded garbage; never stored
                    acc[0][j] += x0 * wv;
                    acc[1][j] += x1 * wv;
                    acc[2][j] += x2 * wv;
                    acc[3][j] += x3 * wv;
                }
            }
        }
    }
#pragma unroll
    for (int r = 0; r < 4; ++r) {
        int row = rowBase + r;
        if (row >= n) continue;
        for (int j = 0; j < nj; ++j) {
            int cc = lane + 32 * j;
            if (cc < Cout) {
                float v = acc[r][j];
                if (bias) v += bias[cc];
                if (doRelu) v = fmaxf(v, 0.f);
                out[(long long)row * Cout + cc] = v;
            }
        }
    }
}

// pack [Wmu | Wls] -> g_Wc[Cin=43][32]
__global__ void k_packw(const float* __restrict__ Wmu, const float* __restrict__ Wls) {
    int i = blockIdx.x * blockDim.x + threadIdx.x;
    if (i >= C2 * 2 * CO) return;
    int kin = i / (2 * CO), c = i % (2 * CO);
    g_Wc[i] = (c < CO) ? Wmu[kin * CO + c] : Wls[kin * CO + (c - CO)];
}

// out = agg + dis2^2 * y + bias, split into mu / logstd halves
__global__ void k_final(const float* __restrict__ bmu, const float* __restrict__ bls,
                        float* __restrict__ outmu, float* __restrict__ outls, int n) {
    int i = blockIdx.x * blockDim.x + threadIdx.x;
    if (i >= n * CO) return;
    int node = i >> 4, c = i & 15;
    float d2 = g_dis2[node];
    float s = d2 * d2;
    outmu[i] = g_agg[node * 32 + c]      + s * g_y[node * 32 + c]      + bmu[c];
    outls[i] = g_agg[node * 32 + 16 + c] + s * g_y[node * 32 + 16 + c] + bls[c];
}

// ---------------- host launch ----------------
extern "C" void kernel_launch(void* const* d_in, const int* in_sizes, int n_in,
                              void* d_out, int out_size) {
    (void)n_in; (void)out_size;
    const float* x    = (const float*)d_in[0];
    const int*   ei32 = (const int*)d_in[1];   // int32 words; layout auto-detected
    const float* W1   = (const float*)d_in[2];
    const float* b1   = (const float*)d_in[3];
    const float* W2   = (const float*)d_in[4];
    const float* b2   = (const float*)d_in[5];
    const float* Wmu  = (const float*)d_in[6];
    const float* bmu  = (const float*)d_in[7];
    const float* Wls  = (const float*)d_in[8];
    const float* bls  = (const float*)d_in[9];
    float* out = (float*)d_out;

    int n = in_sizes[0] / C0;   // 50000
    int e = in_sizes[1] / 2;    // 800000 (element count is dtype-agnostic)
    int nb = (n + SCAN_T - 1) / SCAN_T;

    // --- graph structure ---
    k_detect<<<1, 256>>>(ei32);
    k_zero_deg<<<(n + 255) / 256, 256>>>(n);
    k_hist<<<(e + 255) / 256, 256>>>(ei32, e, n);
    k_scan1<<<nb, SCAN_T>>>(n);
    k_scan2<<<1, SCAN_T>>>(nb);
    k_scan3<<<nb, SCAN_T>>>(n, nb);
    k_scatter<<<(e + 255) / 256, 256>>>(ei32, e, n);

    dim3 pblk(32, 8);                 // 8 warps = 8 nodes per block
    int pgrid = (n + 7) / 8;

    // --- TAG layer 1 (C=96 -> 70) ---
    {
        k_prop<<<pgrid, pblk>>>(x, SEL_EXT, SEL_A, 0, C0 / 2, n);
        k_prop<<<pgrid, pblk>>>(0, SEL_A,   SEL_B, 0, C0 / 2, n);
        k_prop<<<pgrid, pblk>>>(0, SEL_B,   SEL_C, 0, C0 / 2, n);
        size_t sm = (size_t)(C0 * C1 + 32 + 32 * C0) * sizeof(float);
        k_mm<<<(n + 31) / 32, 256, sm>>>(x, SEL_EXT, SEL_A, SEL_B, SEL_C,
                                         W1, 0, b1, SEL_L1, n, C0, C1, 4, 1);
    }

    // --- TAG layer 2 (C=70 -> 43) ---
    {
        k_prop<<<pgrid, pblk>>>(0, SEL_L1, SEL_A, 0, C1 / 2, n);
        k_prop<<<pgrid, pblk>>>(0, SEL_A,  SEL_B, 0, C1 / 2, n);
        k_prop<<<pgrid, pblk>>>(0, SEL_B,  SEL_C, 0, C1 / 2, n);
        size_t sm = (size_t)(C1 * C2 + 32 + 32 * C1) * sizeof(float);
        k_mm<<<(n + 31) / 32, 256, sm>>>(0, SEL_L1, SEL_A, SEL_B, SEL_C,
                                         W2, 0, b2, SEL_L2, n, C1, C2, 4, 1);
    }

    // --- dual GCN head (fused mu+logstd, C=43 -> 32) ---
    {
        k_packw<<<(C2 * 2 * CO + 255) / 256, 256>>>(Wmu, Wls);
        size_t sm = (size_t)(C2 * 2 * CO + 32 + 32 * C2) * sizeof(float);
        k_mm<<<(n + 31) / 32, 256, sm>>>(0, SEL_L2, SEL_L2, SEL_L2, SEL_L2,
                                         0, 1, (const float*)0, SEL_Y,
                                         n, C2, 2 * CO, 1, 0);
        k_prop<<<pgrid, pblk>>>(0, SEL_Y, SEL_AGG, 1, CO, n);
        k_final<<<(n * CO + 255) / 256, 256>>>(bmu, bls, out, out + (size_t)n * CO, n);
    }
}

// round 13
// speedup vs baseline: 1.3532x; 1.0524x over previous
#include <cuda_runtime.h>

// Problem constants (fixed by the dataset)
#define NN 50000
#define EE 800000
#define C0 96   // input channels
#define C1 70   // layer-1 out
#define C2 43   // layer-2 out
#define C2P 44  // padded stride for layer-2 buffers (float2-friendly)
#define CO 16   // mu / logstd channels

#define SCAN_T 256
#define SCAN_NB ((NN + SCAN_T - 1) / SCAN_T)   // 196

// ---------------- scratch (static __device__ arrays; no allocations) ----------------
__device__ int   g_is64;          // 1 if edge_index buffer is int64 words
__device__ int   g_deg[NN];
__device__ float g_dis[NN];
__device__ float g_dis2[NN];
__device__ int   g_rowptr[NN + 1];
__device__ int   g_cursor[NN];
__device__ int   g_blkinc[SCAN_NB];
__device__ int   g_srcs[EE];
__device__ float g_wtag[EE];
__device__ float g_wgcn[EE];
__device__ float g_bufA[NN * C1];   // Horner work buffers (max width 70)
__device__ float g_bufB[NN * C1];
__device__ float g_bufC[NN * C1];
__device__ float g_bufD[NN * C1];
__device__ float g_l1out[NN * C1];
__device__ float g_l2out[NN * C2P];
__device__ float g_y[NN * 2 * CO];
__device__ float g_agg[NN * 2 * CO];
__device__ float g_Wc[C2 * 2 * CO];

// Buffer selectors (device-resolved; host never touches symbol addresses).
#define SEL_A    0
#define SEL_B    1
#define SEL_C    2
#define SEL_D    3
#define SEL_L1   4
#define SEL_L2   5
#define SEL_Y    6
#define SEL_AGG  7
#define SEL_EXT  (-1)
#define SEL_NONE (-2)

__device__ __forceinline__ float* selbuf(int s) {
    switch (s) {
        case SEL_A:   return g_bufA;
        case SEL_B:   return g_bufB;
        case SEL_C:   return g_bufC;
        case SEL_D:   return g_bufD;
        case SEL_L1:  return g_l1out;
        case SEL_L2:  return g_l2out;
        case SEL_Y:   return g_y;
        case SEL_AGG: return g_agg;
    }
    return 0;
}

// row / col index of edge e under either word layout
__device__ __forceinline__ int load_row(const int* ei32, int e_cnt, int e) {
    return g_is64 ? ei32[2 * (long long)e] : ei32[e];
}
__device__ __forceinline__ int load_col(const int* ei32, int e_cnt, int e) {
    return g_is64 ? ei32[2 * ((long long)e_cnt + e)] : ei32[e_cnt + e];
}

// ---------------- dtype detection ----------------
__global__ void k_detect(const int* __restrict__ ei32) {
    __shared__ int any;
    if (threadIdx.x == 0) any = 0;
    __syncthreads();
    int local = 0;
    for (int i = threadIdx.x; i < 4096; i += blockDim.x)
        if (ei32[2 * i + 1] != 0) local = 1;
    if (local) atomicOr(&any, 1);
    __syncthreads();
    if (threadIdx.x == 0) g_is64 = (any == 0) ? 1 : 0;
}

// ---------------- graph-structure kernels ----------------
__global__ void k_zero_deg(int n) {
    int i = blockIdx.x * blockDim.x + threadIdx.x;
    if (i < n) g_deg[i] = 0;
}

__global__ void k_hist(const int* __restrict__ ei32, int e_cnt, int n) {
    int e = blockIdx.x * blockDim.x + threadIdx.x;
    if (e >= e_cnt) return;
    int r = load_row(ei32, e_cnt, e);
    int c = load_col(ei32, e_cnt, e);
    if ((unsigned)r < (unsigned)n && (unsigned)c < (unsigned)n)
        atomicAdd(&g_deg[c], 1);
}

// --- decoupled 3-phase scan ---
__global__ void k_scan1(int n) {
    __shared__ int sh[SCAN_T];
    int i = blockIdx.x * SCAN_T + threadIdx.x;
    int v = (i < n) ? g_deg[i] : 0;
    sh[threadIdx.x] = v;
    __syncthreads();
    for (int off = SCAN_T / 2; off > 0; off >>= 1) {
        if (threadIdx.x < off) sh[threadIdx.x] += sh[threadIdx.x + off];
        __syncthreads();
    }
    if (threadIdx.x == 0) g_blkinc[blockIdx.x] = sh[0];
}
__global__ void k_scan2(int nb) {
    __shared__ int sh[SCAN_T];
    int t = threadIdx.x;
    int v = (t < nb) ? g_blkinc[t] : 0;
    sh[t] = v;
    __syncthreads();
    for (int off = 1; off < SCAN_T; off <<= 1) {
        int u = (t >= off) ? sh[t - off] : 0;
        __syncthreads();
        sh[t] += u;
        __syncthreads();
    }
    if (t < nb) g_blkinc[t] = sh[t];
}
__global__ void k_scan3(int n, int nb) {
    __shared__ int sh[SCAN_T];
    int t = threadIdx.x;
    int i = blockIdx.x * SCAN_T + t;
    int v = (i < n) ? g_deg[i] : 0;
    sh[t] = v;
    __syncthreads();
    for (int off = 1; off < SCAN_T; off <<= 1) {
        int u = (t >= off) ? sh[t - off] : 0;
        __syncthreads();
        sh[t] += u;
        __syncthreads();
    }
    int blkoff = (blockIdx.x > 0) ? g_blkinc[blockIdx.x - 1] : 0;
    if (i < n) {
        int ex = blkoff + sh[t] - v;    // exclusive
        g_rowptr[i] = ex;
        g_cursor[i] = ex;
        g_dis[i]  = (v > 0) ? rsqrtf((float)v) : 0.f;
        g_dis2[i] = rsqrtf((float)v + 1.f);
    }
    if (blockIdx.x == nb - 1 && t == 0) g_rowptr[n] = g_blkinc[nb - 1];
}

__global__ void k_scatter(const int* __restrict__ ei32, int e_cnt, int n) {
    int e = blockIdx.x * blockDim.x + threadIdx.x;
    if (e >= e_cnt) return;
    int r = load_row(ei32, e_cnt, e);
    int c = load_col(ei32, e_cnt, e);
    if ((unsigned)r >= (unsigned)n || (unsigned)c >= (unsigned)n) return;
    int pos = atomicAdd(&g_cursor[c], 1);
    g_srcs[pos] = r;
    g_wtag[pos] = g_dis[r]  * g_dis[c];
    g_wgcn[pos] = g_dis2[r] * g_dis2[c];
}

// ---------------- propagation: warp-per-node, float2 slots, fused epilogue ----------
// hout[node] = base[node] + sum_e w[e]*hin[src[e]]  (+bias, relu optional)
// blockDim = (32, 8). Lane owns float2 slots {lane, lane+32}; Cv = stride/2 <= 64.
// Creal = valid float channels (bias guard for odd widths).
__global__ void k_prop(int hinSel, int baseSel, int houtSel, int wSel, int Cv,
                       const float* __restrict__ bias, int Creal, int doRelu, int n) {
    const float2* __restrict__ hin = (const float2*)selbuf(hinSel);
    const float2* __restrict__ base = (baseSel >= 0) ? (const float2*)selbuf(baseSel) : 0;
    float2* hout = (float2*)selbuf(houtSel);
    const float* __restrict__ w = (wSel == 0) ? g_wtag : g_wgcn;
    int node = blockIdx.x * blockDim.y + threadIdx.y;
    if (node >= n) return;
    int lane = threadIdx.x;
    int c0 = lane, c1 = lane + 32;
    bool h0 = (c0 < Cv), h1 = (c1 < Cv);
    int beg = g_rowptr[node], end = g_rowptr[node + 1];

    float ax0 = 0.f, ay0 = 0.f, ax1 = 0.f, ay1 = 0.f;   // slot c0
    float bx0 = 0.f, by0 = 0.f, bx1 = 0.f, by1 = 0.f;   // slot c1
    int e = beg;
    for (; e + 1 < end; e += 2) {
        int s0 = g_srcs[e], s1 = g_srcs[e + 1];          // warp-uniform broadcast
        float w0 = w[e], w1 = w[e + 1];
        long long r0 = (long long)s0 * Cv, r1 = (long long)s1 * Cv;
        if (h0) {
            float2 v0 = hin[r0 + c0]; ax0 += w0 * v0.x; ay0 += w0 * v0.y;
            float2 v1 = hin[r1 + c0]; ax1 += w1 * v1.x; ay1 += w1 * v1.y;
        }
        if (h1) {
            float2 u0 = hin[r0 + c1]; bx0 += w0 * u0.x; by0 += w0 * u0.y;
            float2 u1 = hin[r1 + c1]; bx1 += w1 * u1.x; by1 += w1 * u1.y;
        }
    }
    if (e < end) {
        int s = g_srcs[e];
        float we = w[e];
        long long r = (long long)s * Cv;
        if (h0) { float2 v = hin[r + c0]; ax0 += we * v.x; ay0 += we * v.y; }
        if (h1) { float2 u = hin[r + c1]; bx0 += we * u.x; by0 += we * u.y; }
    }
    long long o = (long long)node * Cv;
    if (h0) {
        float2 r; r.x = ax0 + ax1; r.y = ay0 + ay1;
        if (base) { float2 b = base[o + c0]; r.x += b.x; r.y += b.y; }
        if (bias) { r.x += bias[2 * c0]; if (2 * c0 + 1 < Creal) r.y += bias[2 * c0 + 1]; }
        if (doRelu) { r.x = fmaxf(r.x, 0.f); r.y = fmaxf(r.y, 0.f); }
        hout[o + c0] = r;
    }
    if (h1) {
        float2 r; r.x = bx0 + bx1; r.y = by0 + by1;
        if (base) { float2 b = base[o + c1]; r.x += b.x; r.y += b.y; }
        if (bias) { r.x += bias[2 * c1]; if (2 * c1 + 1 < Creal) r.y += bias[2 * c1 + 1]; }
        if (doRelu) { r.x = fmaxf(r.x, 0.f); r.y = fmaxf(r.y, 0.f); }
        hout[o + c1] = r;
    }
}

// ---------------- multi-weight projection: out_k = h @ W[k], k < nK ------------------
// Stages 32 input rows in smem ONCE, then loops over weight matrices.
// Block: 256 threads = 8 warps x 4 rows.
__global__ void k_mmP(const float* __restrict__ h_ext, int hinSel, int strideIn,
                      const float* __restrict__ W_ext, int Wsel,
                      int o0, int o1, int o2, int o3, int strideOut,
                      int n, int Cin, int Cout, int nK) {
    extern __shared__ float smem[];
    float* Wst = smem;                        // Cin*Cout + 32 pad (OOB-safe reads)
    float* Rst = smem + Cin * Cout + 32;      // 32 rows * Cin
    const float* hk = (hinSel == SEL_EXT) ? h_ext : selbuf(hinSel);
    const float* W  = (Wsel == 1) ? g_Wc : W_ext;
    int lane = threadIdx.x & 31;
    int wid  = threadIdx.x >> 5;
    int rowBase = blockIdx.x * 32 + wid * 4;
    int outs[4] = {o0, o1, o2, o3};
    int nj = (Cout + 31) >> 5;

    // stage input rows once
#pragma unroll
    for (int r = 0; r < 4; ++r) {
        int row = rowBase + r;
        float* dst = &Rst[(wid * 4 + r) * Cin];
        if (row < n) {
            for (int i = lane; i < Cin; i += 32) dst[i] = hk[(long long)row * strideIn + i];
        } else {
            for (int i = lane; i < Cin; i += 32) dst[i] = 0.f;
        }
    }

    for (int k = 0; k < nK; ++k) {
        __syncthreads();
        for (int i = threadIdx.x; i < Cin * Cout; i += blockDim.x)
            Wst[i] = W[k * Cin * Cout + i];
        __syncthreads();
        float acc[4][3];
#pragma unroll
        for (int r = 0; r < 4; ++r) { acc[r][0] = 0.f; acc[r][1] = 0.f; acc[r][2] = 0.f; }
        for (int kin = 0; kin < Cin; ++kin) {
            float x0 = Rst[(wid * 4 + 0) * Cin + kin];
            float x1 = Rst[(wid * 4 + 1) * Cin + kin];
            float x2 = Rst[(wid * 4 + 2) * Cin + kin];
            float x3 = Rst[(wid * 4 + 3) * Cin + kin];
            const float* wrow = &Wst[kin * Cout + lane];
#pragma unroll
            for (int j = 0; j < 3; ++j) {
                if (j < nj) {
                    float wv = wrow[32 * j];
                    acc[0][j] += x0 * wv;
                    acc[1][j] += x1 * wv;
                    acc[2][j] += x2 * wv;
                    acc[3][j] += x3 * wv;
                }
            }
        }
        float* out = selbuf(outs[k]);
#pragma unroll
        for (int r = 0; r < 4; ++r) {
            int row = rowBase + r;
            if (row >= n) continue;
            for (int j = 0; j < nj; ++j) {
                int cc = lane + 32 * j;
                if (cc < Cout) out[(long long)row * strideOut + cc] = acc[r][j];
            }
        }
    }
}

// pack [Wmu | Wls] -> g_Wc[Cin=43][32]
__global__ void k_packw(const float* __restrict__ Wmu, const float* __restrict__ Wls) {
    int i = blockIdx.x * blockDim.x + threadIdx.x;
    if (i >= C2 * 2 * CO) return;
    int kin = i / (2 * CO), c = i % (2 * CO);
    g_Wc[i] = (c < CO) ? Wmu[kin * CO + c] : Wls[kin * CO + (c - CO)];
}

// out = agg + dis2^2 * y + bias, split into mu / logstd halves
__global__ void k_final(const float* __restrict__ bmu, const float* __restrict__ bls,
                        float* __restrict__ outmu, float* __restrict__ outls, int n) {
    int i = blockIdx.x * blockDim.x + threadIdx.x;
    if (i >= n * CO) return;
    int node = i >> 4, c = i & 15;
    float d2 = g_dis2[node];
    float s = d2 * d2;
    outmu[i] = g_agg[node * 32 + c]      + s * g_y[node * 32 + c]      + bmu[c];
    outls[i] = g_agg[node * 32 + 16 + c] + s * g_y[node * 32 + 16 + c] + bls[c];
}

// ---------------- host launch ----------------
extern "C" void kernel_launch(void* const* d_in, const int* in_sizes, int n_in,
                              void* d_out, int out_size) {
    (void)n_in; (void)out_size;
    const float* x    = (const float*)d_in[0];
    const int*   ei32 = (const int*)d_in[1];   // int32 words; layout auto-detected
    const float* W1   = (const float*)d_in[2];
    const float* b1   = (const float*)d_in[3];
    const float* W2   = (const float*)d_in[4];
    const float* b2   = (const float*)d_in[5];
    const float* Wmu  = (const float*)d_in[6];
    const float* bmu  = (const float*)d_in[7];
    const float* Wls  = (const float*)d_in[8];
    const float* bls  = (const float*)d_in[9];
    float* out = (float*)d_out;

    int n = in_sizes[0] / C0;   // 50000
    int e = in_sizes[1] / 2;    // 800000
    int nb = (n + SCAN_T - 1) / SCAN_T;

    // --- graph structure ---
    k_detect<<<1, 256>>>(ei32);
    k_zero_deg<<<(n + 255) / 256, 256>>>(n);
    k_hist<<<(e + 255) / 256, 256>>>(ei32, e, n);
    k_scan1<<<nb, SCAN_T>>>(n);
    k_scan2<<<1, SCAN_T>>>(nb);
    k_scan3<<<nb, SCAN_T>>>(n, nb);
    k_scatter<<<(e + 255) / 256, 256>>>(ei32, e, n);

    dim3 pblk(32, 8);                 // 8 warps = 8 nodes per block
    int pgrid = (n + 7) / 8;
    int mgrid = (n + 31) / 32;

    // --- TAG layer 1 (Horner): out = xW0 + A(xW1 + A(xW2 + A(xW3))) ---
    {
        // projections: P0->D, P1->C, P2->B, P3->A  (W layout is [k][Cin][Cout], k=0..3)
        size_t sm = (size_t)(C0 * C1 + 32 + 32 * C0) * sizeof(float);
        k_mmP<<<mgrid, 256, sm>>>(x, SEL_EXT, C0, W1, 0,
                                  SEL_D, SEL_C, SEL_B, SEL_A, C1, n, C0, C1, 4);
        // z2 = P2 + A P3 ; z1 = P1 + A z2 ; l1 = relu(P0 + A z1 + b1)
        k_prop<<<pgrid, pblk>>>(SEL_A, SEL_B, SEL_B, 0, C1 / 2, 0, C1, 0, n);
        k_prop<<<pgrid, pblk>>>(SEL_B, SEL_C, SEL_C, 0, C1 / 2, 0, C1, 0, n);
        k_prop<<<pgrid, pblk>>>(SEL_C, SEL_D, SEL_L1, 0, C1 / 2, b1, C1, 1, n);
    }

    // --- TAG layer 2 (Horner, stride padded 43->44) ---
    {
        size_t sm = (size_t)(C1 * C2 + 32 + 32 * C1) * sizeof(float);
        k_mmP<<<mgrid, 256, sm>>>(0, SEL_L1, C1, W2, 0,
                                  SEL_D, SEL_C, SEL_B, SEL_A, C2P, n, C1, C2, 4);
        k_prop<<<pgrid, pblk>>>(SEL_A, SEL_B, SEL_B, 0, C2P / 2, 0, C2, 0, n);
        k_prop<<<pgrid, pblk>>>(SEL_B, SEL_C, SEL_C, 0, C2P / 2, 0, C2, 0, n);
        k_prop<<<pgrid, pblk>>>(SEL_C, SEL_D, SEL_L2, 0, C2P / 2, b2, C2, 1, n);
    }

    // --- dual GCN head (fused mu+logstd, C=43 -> 32) ---
    {
        k_packw<<<(C2 * 2 * CO + 255) / 256, 256>>>(Wmu, Wls);
        size_t sm = (size_t)(C2 * 2 * CO + 32 + 32 * C2) * sizeof(float);
        k_mmP<<<mgrid, 256, sm>>>(0, SEL_L2, C2P, 0, 1,
                                  SEL_Y, SEL_Y, SEL_Y, SEL_Y, 2 * CO, n, C2, 2 * CO, 1);
        k_prop<<<pgrid, pblk>>>(SEL_Y, SEL_NONE, SEL_AGG, 1, CO, 0, 2 * CO, 0, n);
        k_final<<<(n * CO + 255) / 256, 256>>>(bmu, bls, out, out + (size_t)n * CO, n);
    }
}

// round 14
// speedup vs baseline: 1.3776x; 1.0180x over previous
#include <cuda_runtime.h>

// Problem constants (fixed by the dataset)
#define NN 50000
#define EE 800000
#define C0 96   // input channels
#define C1 70   // layer-1 out
#define C2 43   // layer-2 out
#define CO 16   // mu / logstd channels

// float4 strides (in float4 units)
#define S1 18   // 72 floats  (layer-1 width 70 + pad)
#define S2 11   // 44 floats  (layer-2 width 43 + pad)
#define SH 8    // 32 floats  (head width 32)

#define SCAN_T 256
#define SCAN_NB ((NN + SCAN_T - 1) / SCAN_T)   // 196

// ---------------- scratch (static __device__ arrays; no allocations) ----------------
__device__ int    g_is64;
__device__ int    g_deg[NN];
__device__ float  g_dis[NN];
__device__ float  g_dis2[NN];
__device__ int    g_rowptr[NN + 1];
__device__ int    g_cursor[NN];
__device__ int    g_blkinc[SCAN_NB];
__device__ float4 g_erec[EE];          // {src(bits), wtag, wgcn, 0}
__device__ float4 g_b4A[NN * S1];      // Horner work buffers (max stride S1)
__device__ float4 g_b4B[NN * S1];
__device__ float4 g_b4C[NN * S1];
__device__ float4 g_b4D[NN * S1];
__device__ float4 g_l1out[NN * S1];
__device__ float4 g_l2out[NN * S2];
__device__ float4 g_y[NN * SH];
__device__ float4 g_agg[NN * SH];
__device__ float  g_Wc[C2 * 2 * CO];

// Buffer selectors (device-resolved; host never touches symbol addresses).
#define SEL_A    0
#define SEL_B    1
#define SEL_C    2
#define SEL_D    3
#define SEL_L1   4
#define SEL_L2   5
#define SEL_Y    6
#define SEL_AGG  7
#define SEL_EXT  (-1)
#define SEL_NONE (-2)

__device__ __forceinline__ float4* selbuf4(int s) {
    switch (s) {
        case SEL_A:   return g_b4A;
        case SEL_B:   return g_b4B;
        case SEL_C:   return g_b4C;
        case SEL_D:   return g_b4D;
        case SEL_L1:  return g_l1out;
        case SEL_L2:  return g_l2out;
        case SEL_Y:   return g_y;
        case SEL_AGG: return g_agg;
    }
    return 0;
}

// row / col index of edge e under either word layout (int2 loads keep 8B coalescing)
__device__ __forceinline__ int load_row(const int* ei32, int e_cnt, int e) {
    if (g_is64) return ((const int2*)ei32)[e].x;
    return ei32[e];
}
__device__ __forceinline__ int load_col(const int* ei32, int e_cnt, int e) {
    if (g_is64) return ((const int2*)ei32)[(long long)e_cnt + e].x;
    return ei32[e_cnt + e];
}

// ---------------- dtype detection ----------------
__global__ void k_detect(const int* __restrict__ ei32) {
    __shared__ int any;
    if (threadIdx.x == 0) any = 0;
    __syncthreads();
    int local = 0;
    for (int i = threadIdx.x; i < 4096; i += blockDim.x)
        if (ei32[2 * i + 1] != 0) local = 1;
    if (local) atomicOr(&any, 1);
    __syncthreads();
    if (threadIdx.x == 0) g_is64 = (any == 0) ? 1 : 0;
}

// ---------------- graph-structure kernels ----------------
__global__ void k_zero_deg(int n) {
    int i = blockIdx.x * blockDim.x + threadIdx.x;
    if (i < n) g_deg[i] = 0;
}

__global__ void k_hist(const int* __restrict__ ei32, int e_cnt, int n) {
    int e = blockIdx.x * blockDim.x + threadIdx.x;
    if (e >= e_cnt) return;
    int r = load_row(ei32, e_cnt, e);
    int c = load_col(ei32, e_cnt, e);
    if ((unsigned)r < (unsigned)n && (unsigned)c < (unsigned)n)
        atomicAdd(&g_deg[c], 1);
}

// --- decoupled 3-phase scan ---
__global__ void k_scan1(int n) {
    __shared__ int sh[SCAN_T];
    int i = blockIdx.x * SCAN_T + threadIdx.x;
    int v = (i < n) ? g_deg[i] : 0;
    sh[threadIdx.x] = v;
    __syncthreads();
    for (int off = SCAN_T / 2; off > 0; off >>= 1) {
        if (threadIdx.x < off) sh[threadIdx.x] += sh[threadIdx.x + off];
        __syncthreads();
    }
    if (threadIdx.x == 0) g_blkinc[blockIdx.x] = sh[0];
}
__global__ void k_scan2(int nb) {
    __shared__ int sh[SCAN_T];
    int t = threadIdx.x;
    int v = (t < nb) ? g_blkinc[t] : 0;
    sh[t] = v;
    __syncthreads();
    for (int off = 1; off < SCAN_T; off <<= 1) {
        int u = (t >= off) ? sh[t - off] : 0;
        __syncthreads();
        sh[t] += u;
        __syncthreads();
    }
    if (t < nb) g_blkinc[t] = sh[t];
}
__global__ void k_scan3(int n, int nb) {
    __shared__ int sh[SCAN_T];
    int t = threadIdx.x;
    int i = blockIdx.x * SCAN_T + t;
    int v = (i < n) ? g_deg[i] : 0;
    sh[t] = v;
    __syncthreads();
    for (int off = 1; off < SCAN_T; off <<= 1) {
        int u = (t >= off) ? sh[t - off] : 0;
        __syncthreads();
        sh[t] += u;
        __syncthreads();
    }
    int blkoff = (blockIdx.x > 0) ? g_blkinc[blockIdx.x - 1] : 0;
    if (i < n) {
        int ex = blkoff + sh[t] - v;    // exclusive
        g_rowptr[i] = ex;
        g_cursor[i] = ex;
        g_dis[i]  = (v > 0) ? rsqrtf((float)v) : 0.f;
        g_dis2[i] = rsqrtf((float)v + 1.f);
    }
    if (blockIdx.x == nb - 1 && t == 0) g_rowptr[n] = g_blkinc[nb - 1];
}

__global__ void k_scatter(const int* __restrict__ ei32, int e_cnt, int n) {
    int e = blockIdx.x * blockDim.x + threadIdx.x;
    if (e >= e_cnt) return;
    int r = load_row(ei32, e_cnt, e);
    int c = load_col(ei32, e_cnt, e);
    if ((unsigned)r >= (unsigned)n || (unsigned)c >= (unsigned)n) return;
    int pos = atomicAdd(&g_cursor[c], 1);
    float4 v;
    v.x = __int_as_float(r);
    v.y = g_dis[r]  * g_dis[c];
    v.z = g_dis2[r] * g_dis2[c];
    v.w = 0.f;
    g_erec[pos] = v;    // single 16B store
}

// ---------------- propagation: warp-per-node, ONE float4 slot per lane --------------
// hout[node] = base[node] + sum_e w[e]*hin[src[e]]  (+bias, relu optional)
// blockDim = (32, 8). Lane owns float4 slot `lane` (< Cv4 <= 32, uniform predicate).
// Creal = valid float channels (bias/pad guard). wSel: 0 -> wtag, 1 -> wgcn.
__global__ void k_prop(int hinSel, int baseSel, int houtSel, int wSel, int Cv4,
                       const float* __restrict__ bias, int Creal, int doRelu, int n) {
    const float4* __restrict__ hin = selbuf4(hinSel);
    const float4* __restrict__ base = (baseSel >= 0) ? selbuf4(baseSel) : 0;
    float4* hout = selbuf4(houtSel);
    int node = blockIdx.x * blockDim.y + threadIdx.y;
    if (node >= n) return;
    int lane = threadIdx.x;
    bool act = (lane < Cv4);
    int beg = g_rowptr[node], end = g_rowptr[node + 1];

    float4 a0 = make_float4(0.f, 0.f, 0.f, 0.f);
    float4 a1 = make_float4(0.f, 0.f, 0.f, 0.f);
    int e = beg;
    for (; e + 1 < end; e += 2) {
        float4 r0 = g_erec[e];        // warp-uniform broadcast, 1 LDG.128
        float4 r1 = g_erec[e + 1];
        int s0 = __float_as_int(r0.x), s1 = __float_as_int(r1.x);
        float w0 = wSel ? r0.z : r0.y;
        float w1 = wSel ? r1.z : r1.y;
        if (act) {
            float4 v0 = hin[(long long)s0 * Cv4 + lane];
            float4 v1 = hin[(long long)s1 * Cv4 + lane];
            a0.x += w0 * v0.x; a0.y += w0 * v0.y; a0.z += w0 * v0.z; a0.w += w0 * v0.w;
            a1.x += w1 * v1.x; a1.y += w1 * v1.y; a1.z += w1 * v1.z; a1.w += w1 * v1.w;
        }
    }
    if (e < end) {
        float4 r0 = g_erec[e];
        int s0 = __float_as_int(r0.x);
        float w0 = wSel ? r0.z : r0.y;
        if (act) {
            float4 v0 = hin[(long long)s0 * Cv4 + lane];
            a0.x += w0 * v0.x; a0.y += w0 * v0.y; a0.z += w0 * v0.z; a0.w += w0 * v0.w;
        }
    }
    if (act) {
        long long o = (long long)node * Cv4 + lane;
        float4 r;
        r.x = a0.x + a1.x; r.y = a0.y + a1.y; r.z = a0.z + a1.z; r.w = a0.w + a1.w;
        if (base) {
            float4 b = base[o];
            r.x += b.x; r.y += b.y; r.z += b.z; r.w += b.w;
        }
        if (bias) {
            int c = 4 * lane;
            if (c + 0 < Creal) r.x += bias[c + 0];
            if (c + 1 < Creal) r.y += bias[c + 1];
            if (c + 2 < Creal) r.z += bias[c + 2];
            if (c + 3 < Creal) r.w += bias[c + 3];
        }
        if (doRelu) {
            r.x = fmaxf(r.x, 0.f); r.y = fmaxf(r.y, 0.f);
            r.z = fmaxf(r.z, 0.f); r.w = fmaxf(r.w, 0.f);
        }
        hout[o] = r;
    }
}

// ---------------- multi-weight projection: out_k = h @ W[k], k < nK ------------------
// Stages 32 input rows in smem ONCE, then loops over weight matrices.
// Block: 256 threads = 8 warps x 4 rows. Strides are in floats.
__global__ void k_mmP(const float* __restrict__ h_ext, int hinSel, int strideIn,
                      const float* __restrict__ W_ext, int Wsel,
                      int o0, int o1, int o2, int o3, int strideOut,
                      int n, int Cin, int Cout, int nK) {
    extern __shared__ float smem[];
    float* Wst = smem;                        // Cin*Cout + 32 pad (OOB-safe reads)
    float* Rst = smem + Cin * Cout + 32;      // 32 rows * Cin
    const float* hk = (hinSel == SEL_EXT) ? h_ext : (const float*)selbuf4(hinSel);
    const float* W  = (Wsel == 1) ? g_Wc : W_ext;
    int lane = threadIdx.x & 31;
    int wid  = threadIdx.x >> 5;
    int rowBase = blockIdx.x * 32 + wid * 4;
    int outs[4] = {o0, o1, o2, o3};
    int nj = (Cout + 31) >> 5;

#pragma unroll
    for (int r = 0; r < 4; ++r) {
        int row = rowBase + r;
        float* dst = &Rst[(wid * 4 + r) * Cin];
        if (row < n) {
            for (int i = lane; i < Cin; i += 32) dst[i] = hk[(long long)row * strideIn + i];
        } else {
            for (int i = lane; i < Cin; i += 32) dst[i] = 0.f;
        }
    }

    for (int k = 0; k < nK; ++k) {
        __syncthreads();
        for (int i = threadIdx.x; i < Cin * Cout; i += blockDim.x)
            Wst[i] = W[k * Cin * Cout + i];
        __syncthreads();
        float acc[4][3];
#pragma unroll
        for (int r = 0; r < 4; ++r) { acc[r][0] = 0.f; acc[r][1] = 0.f; acc[r][2] = 0.f; }
        for (int kin = 0; kin < Cin; ++kin) {
            float x0 = Rst[(wid * 4 + 0) * Cin + kin];
            float x1 = Rst[(wid * 4 + 1) * Cin + kin];
            float x2 = Rst[(wid * 4 + 2) * Cin + kin];
            float x3 = Rst[(wid * 4 + 3) * Cin + kin];
            const float* wrow = &Wst[kin * Cout + lane];
#pragma unroll
            for (int j = 0; j < 3; ++j) {
                if (j < nj) {
                    float wv = wrow[32 * j];
                    acc[0][j] += x0 * wv;
                    acc[1][j] += x1 * wv;
                    acc[2][j] += x2 * wv;
                    acc[3][j] += x3 * wv;
                }
            }
        }
        float* out = (float*)selbuf4(outs[k]);
#pragma unroll
        for (int r = 0; r < 4; ++r) {
            int row = rowBase + r;
            if (row >= n) continue;
            for (int j = 0; j < nj; ++j) {
                int cc = lane + 32 * j;
                if (cc < Cout) out[(long long)row * strideOut + cc] = acc[r][j];
            }
        }
    }
}

// pack [Wmu | Wls] -> g_Wc[Cin=43][32]
__global__ void k_packw(const float* __restrict__ Wmu, const float* __restrict__ Wls) {
    int i = blockIdx.x * blockDim.x + threadIdx.x;
    if (i >= C2 * 2 * CO) return;
    int kin = i / (2 * CO), c = i % (2 * CO);
    g_Wc[i] = (c < CO) ? Wmu[kin * CO + c] : Wls[kin * CO + (c - CO)];
}

// out = agg + dis2^2 * y + bias, split into mu / logstd halves
__global__ void k_final(const float* __restrict__ bmu, const float* __restrict__ bls,
                        float* __restrict__ outmu, float* __restrict__ outls, int n) {
    int i = blockIdx.x * blockDim.x + threadIdx.x;
    if (i >= n * CO) return;
    int node = i >> 4, c = i & 15;
    const float* y = (const float*)g_y;
    const float* agg = (const float*)g_agg;
    float d2 = g_dis2[node];
    float s = d2 * d2;
    outmu[i] = agg[node * 32 + c]      + s * y[node * 32 + c]      + bmu[c];
    outls[i] = agg[node * 32 + 16 + c] + s * y[node * 32 + 16 + c] + bls[c];
}

// ---------------- host launch ----------------
extern "C" void kernel_launch(void* const* d_in, const int* in_sizes, int n_in,
                              void* d_out, int out_size) {
    (void)n_in; (void)out_size;
    const float* x    = (const float*)d_in[0];
    const int*   ei32 = (const int*)d_in[1];   // int32 words; layout auto-detected
    const float* W1   = (const float*)d_in[2];
    const float* b1   = (const float*)d_in[3];
    const float* W2   = (const float*)d_in[4];
    const float* b2   = (const float*)d_in[5];
    const float* Wmu  = (const float*)d_in[6];
    const float* bmu  = (const float*)d_in[7];
    const float* Wls  = (const float*)d_in[8];
    const float* bls  = (const float*)d_in[9];
    float* out = (float*)d_out;

    int n = in_sizes[0] / C0;   // 50000
    int e = in_sizes[1] / 2;    // 800000
    int nb = (n + SCAN_T - 1) / SCAN_T;

    // --- graph structure ---
    k_detect<<<1, 256>>>(ei32);
    k_zero_deg<<<(n + 255) / 256, 256>>>(n);
    k_hist<<<(e + 255) / 256, 256>>>(ei32, e, n);
    k_scan1<<<nb, SCAN_T>>>(n);
    k_scan2<<<1, SCAN_T>>>(nb);
    k_scan3<<<nb, SCAN_T>>>(n, nb);
    k_scatter<<<(e + 255) / 256, 256>>>(ei32, e, n);

    dim3 pblk(32, 8);                 // 8 warps = 8 nodes per block
    int pgrid = (n + 7) / 8;
    int mgrid = (n + 31) / 32;

    // --- TAG layer 1 (Horner): out = xW0 + A(xW1 + A(xW2 + A(xW3))) ---
    {
        size_t sm = (size_t)(C0 * C1 + 32 + 32 * C0) * sizeof(float);
        k_mmP<<<mgrid, 256, sm>>>(x, SEL_EXT, C0, W1, 0,
                                  SEL_D, SEL_C, SEL_B, SEL_A, 4 * S1, n, C0, C1, 4);
        k_prop<<<pgrid, pblk>>>(SEL_A, SEL_B, SEL_B, 0, S1, 0, C1, 0, n);
        k_prop<<<pgrid, pblk>>>(SEL_B, SEL_C, SEL_C, 0, S1, 0, C1, 0, n);
        k_prop<<<pgrid, pblk>>>(SEL_C, SEL_D, SEL_L1, 0, S1, b1, C1, 1, n);
    }

    // --- TAG layer 2 (Horner, stride 44) ---
    {
        size_t sm = (size_t)(C1 * C2 + 32 + 32 * C1) * sizeof(float);
        k_mmP<<<mgrid, 256, sm>>>(0, SEL_L1, 4 * S1, W2, 0,
                                  SEL_D, SEL_C, SEL_B, SEL_A, 4 * S2, n, C1, C2, 4);
        k_prop<<<pgrid, pblk>>>(SEL_A, SEL_B, SEL_B, 0, S2, 0, C2, 0, n);
        k_prop<<<pgrid, pblk>>>(SEL_B, SEL_C, SEL_C, 0, S2, 0, C2, 0, n);
        k_prop<<<pgrid, pblk>>>(SEL_C, SEL_D, SEL_L2, 0, S2, b2, C2, 1, n);
    }

    // --- dual GCN head (fused mu+logstd, C=43 -> 32) ---
    {
        k_packw<<<(C2 * 2 * CO + 255) / 256, 256>>>(Wmu, Wls);
        size_t sm = (size_t)(C2 * 2 * CO + 32 + 32 * C2) * sizeof(float);
        k_mmP<<<mgrid, 256, sm>>>(0, SEL_L2, 4 * S2, 0, 1,
                                  SEL_Y, SEL_Y, SEL_Y, SEL_Y, 4 * SH, n, C2, 2 * CO, 1);
        k_prop<<<pgrid, pblk>>>(SEL_Y, SEL_NONE, SEL_AGG, 1, SH, 0, 2 * CO, 0, n);
        k_final<<<(n * CO + 255) / 256, 256>>>(bmu, bls, out, out + (size_t)n * CO, n);
    }
}